// round 11
// baseline (speedup 1.0000x reference)
#include <cuda_runtime.h>
#include <cuda_fp16.h>

#define C_IN  64
#define C_MID 64
#define C_OUT 128
#define N_MAX 100000
#define EPS_BN 1e-5f

typedef unsigned long long ull;

// ---- scratch (device globals; no allocations allowed) ----
__device__ int    g_cnt[N_MAX];
__device__ __align__(16) __half g_Yh[N_MAX * C_MID];    // pre-BN layer-1 activations (fp16)
__device__ __align__(16) __half g_Zh[N_MAX * C_OUT];    // pre-BN layer-2 activations (fp16)
__device__ __align__(16) float g_sum1[C_MID], g_sq1[C_MID];
__device__ __align__(16) float g_sum2[C_OUT], g_sq2[C_OUT];
__device__ __align__(16) float g_s1[C_MID],  g_t1[C_MID];
__device__ __align__(16) float g_s2[C_OUT],  g_t2[C_OUT];
__device__ int   g_is64;

// ---- packed fp32x2 helpers (Blackwell FFMA2; ptxas won't auto-fuse) ----
__device__ __forceinline__ ull pack2(float lo, float hi) {
    ull r; asm("mov.b64 %0, {%1, %2};" : "=l"(r) : "f"(lo), "f"(hi)); return r;
}
__device__ __forceinline__ void unpack2(ull v, float& lo, float& hi) {
    asm("mov.b64 {%0, %1}, %2;" : "=f"(lo), "=f"(hi) : "l"(v));
}
__device__ __forceinline__ ull fma2(ull a, ull b, ull c) {
    ull d; asm("fma.rn.f32x2 %0, %1, %2, %3;" : "=l"(d) : "l"(a), "l"(b), "l"(c)); return d;
}

// ---------------------------------------------------------------------------
__global__ void zero_kernel(int n) {
    int i = blockIdx.x * blockDim.x + threadIdx.x;
    if (i < n) g_cnt[i] = 0;
    if (i < C_MID) { g_sum1[i] = 0.f; g_sq1[i] = 0.f; }
    if (i < C_OUT) { g_sum2[i] = 0.f; g_sq2[i] = 0.f; }
}

// int64 little-endian => odd int32 words (high halves) all zero (values < n).
__global__ void detect_kernel(const void* idxp) {
    const int* w = (const int*)idxp;
    int t = threadIdx.x;
    int any = (w[2 * t + 1] != 0) ? 1 : 0;
    int r = __syncthreads_or(any);
    if (t == 0) g_is64 = (r == 0) ? 1 : 0;
}

__global__ void hist_kernel(const void* idxp, int total) {
    int i = blockIdx.x * blockDim.x + threadIdx.x;
    if (i >= total) return;
    int v;
    if (g_is64) v = (int)((const long long*)idxp)[i];
    else        v = ((const int*)idxp)[i];
    atomicAdd(&g_cnt[v], 1);
}

// ---------------------------------------------------------------------------
// GEMM1: Y = feat @ W1 + b1 (Y stored fp16), plus count-weighted stats.
// Block tile 128r x 64c. Thread: 8 rows (4 f32x2 row-pairs) x 4 cols.
// W pre-duplicated+permuted in shared so each LDS.128 is 16B-lane-stride
// (conflict-free) and the inner loop is pure LDS + FFMA2.
// perm(c) = ((c>>1)&1)*32 + (c>>2)*2 + (c&1); thread tx owns cols 4tx..4tx+3.
#define T1_PAD 132
#define SMEM1_BYTES (C_IN * C_MID * 8 + C_IN * T1_PAD * 4 + 128 * 4 + C_MID * 8)
__global__ void __launch_bounds__(256, 2) gemm1_kernel(const float* __restrict__ feat,
        const float* __restrict__ W1, const float* __restrict__ b1, int n) {
    extern __shared__ char smraw[];
    ull*   Wd   = (ull*)smraw;                              // 32 KB
    float* xs   = (float*)(smraw + C_IN * C_MID * 8);       // 33.8 KB
    float* cnts = xs + C_IN * T1_PAD;                       // 128
    float* sW   = cnts + 128;                               // 64
    float* sQ   = sW + C_MID;                               // 64
    int tid = threadIdx.x;
    int tx = tid & 15, ty = tid >> 4;
    int c0 = tx << 2;          // 4 contiguous cols
    int r0 = ty << 3;          // 8 rows
    int lr = tid & 127;        // loader row
    int dh = (tid >> 7) << 5;  // loader d-half (0/32)
    for (int i = tid; i < C_IN * C_MID; i += 256) {
        int c = i & 63;
        float w = W1[i];
        int perm = ((c >> 1) & 1) * 32 + (c >> 2) * 2 + (c & 1);
        Wd[(i >> 6) * 64 + perm] = pack2(w, w);
    }
    if (tid < C_MID) { sW[tid] = 0.f; sQ[tid] = 0.f; }
    float4 bv = *(const float4*)(b1 + c0);
    float wsum[4] = {0,0,0,0}, wsq[4] = {0,0,0,0};
    int ntiles = (n + 127) >> 7;
    float4 pf[8];
    int tile = blockIdx.x;
    if (tile < ntiles) {
        int gr = (tile << 7) + lr; if (gr >= n) gr = n - 1;
        const float4* p = (const float4*)(feat + (size_t)gr * C_IN + dh);
        #pragma unroll
        for (int u = 0; u < 8; u++) pf[u] = p[u];
    }
    for (; tile < ntiles; tile += gridDim.x) {
        int rbase = tile << 7;
        #pragma unroll
        for (int u = 0; u < 8; u++) {       // conflict-free transpose STS
            int d = dh + (u << 2);
            xs[(d + 0) * T1_PAD + lr] = pf[u].x;
            xs[(d + 1) * T1_PAD + lr] = pf[u].y;
            xs[(d + 2) * T1_PAD + lr] = pf[u].z;
            xs[(d + 3) * T1_PAD + lr] = pf[u].w;
        }
        if (tid < 128) {
            int gr = rbase + tid;
            cnts[tid] = (gr < n) ? (float)g_cnt[gr] : 0.f;
        }
        __syncthreads();
        int nt = tile + gridDim.x;          // prefetch next tile behind FMA
        if (nt < ntiles) {
            int gr = (nt << 7) + lr; if (gr >= n) gr = n - 1;
            const float4* p = (const float4*)(feat + (size_t)gr * C_IN + dh);
            #pragma unroll
            for (int u = 0; u < 8; u++) pf[u] = p[u];
        }
        ull acc[4][4];
        #pragma unroll
        for (int rp = 0; rp < 4; rp++) {
            acc[rp][0] = pack2(bv.x, bv.x); acc[rp][1] = pack2(bv.y, bv.y);
            acc[rp][2] = pack2(bv.z, bv.z); acc[rp][3] = pack2(bv.w, bv.w);
        }
        #pragma unroll 8
        for (int d = 0; d < C_IN; d++) {
            ulonglong2 xA = *(const ulonglong2*)&xs[d * T1_PAD + r0];
            ulonglong2 xB = *(const ulonglong2*)&xs[d * T1_PAD + r0 + 4];
            ulonglong2 wA = *(const ulonglong2*)&Wd[d * 64 + 2 * tx];       // cols c0,c0+1
            ulonglong2 wB = *(const ulonglong2*)&Wd[d * 64 + 32 + 2 * tx];  // cols c0+2,c0+3
            acc[0][0] = fma2(xA.x, wA.x, acc[0][0]); acc[0][1] = fma2(xA.x, wA.y, acc[0][1]);
            acc[0][2] = fma2(xA.x, wB.x, acc[0][2]); acc[0][3] = fma2(xA.x, wB.y, acc[0][3]);
            acc[1][0] = fma2(xA.y, wA.x, acc[1][0]); acc[1][1] = fma2(xA.y, wA.y, acc[1][1]);
            acc[1][2] = fma2(xA.y, wB.x, acc[1][2]); acc[1][3] = fma2(xA.y, wB.y, acc[1][3]);
            acc[2][0] = fma2(xB.x, wA.x, acc[2][0]); acc[2][1] = fma2(xB.x, wA.y, acc[2][1]);
            acc[2][2] = fma2(xB.x, wB.x, acc[2][2]); acc[2][3] = fma2(xB.x, wB.y, acc[2][3]);
            acc[3][0] = fma2(xB.y, wA.x, acc[3][0]); acc[3][1] = fma2(xB.y, wA.y, acc[3][1]);
            acc[3][2] = fma2(xB.y, wB.x, acc[3][2]); acc[3][3] = fma2(xB.y, wB.y, acc[3][3]);
        }
        #pragma unroll
        for (int rp = 0; rp < 4; rp++) {
            int rA = rbase + r0 + (rp << 1);
            float ya[4], yb[4];
            #pragma unroll
            for (int j = 0; j < 4; j++) unpack2(acc[rp][j], ya[j], yb[j]);
            if (rA < n) {
                __half2 h0 = __floats2half2_rn(ya[0], ya[1]);
                __half2 h1 = __floats2half2_rn(ya[2], ya[3]);
                uint2 u; u.x = *reinterpret_cast<unsigned*>(&h0);
                u.y = *reinterpret_cast<unsigned*>(&h1);
                *(uint2*)(g_Yh + (size_t)rA * C_MID + c0) = u;
                float w = cnts[r0 + (rp << 1)];
                #pragma unroll
                for (int j = 0; j < 4; j++) {
                    wsum[j] = fmaf(w, ya[j], wsum[j]);
                    wsq[j]  = fmaf(w, ya[j] * ya[j], wsq[j]);
                }
            }
            if (rA + 1 < n) {
                __half2 h0 = __floats2half2_rn(yb[0], yb[1]);
                __half2 h1 = __floats2half2_rn(yb[2], yb[3]);
                uint2 u; u.x = *reinterpret_cast<unsigned*>(&h0);
                u.y = *reinterpret_cast<unsigned*>(&h1);
                *(uint2*)(g_Yh + (size_t)(rA + 1) * C_MID + c0) = u;
                float w = cnts[r0 + (rp << 1) + 1];
                #pragma unroll
                for (int j = 0; j < 4; j++) {
                    wsum[j] = fmaf(w, yb[j], wsum[j]);
                    wsq[j]  = fmaf(w, yb[j] * yb[j], wsq[j]);
                }
            }
        }
        __syncthreads();
    }
    #pragma unroll
    for (int j = 0; j < 4; j++) {
        atomicAdd(&sW[c0 + j], wsum[j]);
        atomicAdd(&sQ[c0 + j], wsq[j]);
    }
    __syncthreads();
    if (tid < C_MID) {
        atomicAdd(&g_sum1[tid], sW[tid]);
        atomicAdd(&g_sq1[tid],  sQ[tid]);
    }
}

__global__ void finalize1_kernel(const float* __restrict__ g1,
                                 const float* __restrict__ be1, float invN) {
    int c = threadIdx.x;  // 64
    float mu  = g_sum1[c] * invN;
    float var = g_sq1[c] * invN - mu * mu;
    float s = g1[c] * rsqrtf(var + EPS_BN);
    g_s1[c] = s;
    g_t1[c] = be1[c] - mu * s;
}

// ---------------------------------------------------------------------------
// GEMM2: H = relu(Yh*s1+t1) fused into loader; Z = H @ W2 + b2; Z stored fp16.
// Block tile 128r x 128c. Thread: 8 rows (4 pairs) x 8 cols, dup-permuted W.
// perm2(c) = ((c>>1)&3)*32 + (c>>3)*2 + (c&1); thread tx owns cols 8tx..8tx+7.
#define T2_PAD 132
#define SMEM2_BYTES (C_MID * C_OUT * 8 + C_MID * T2_PAD * 4 + (C_MID*2 + 128 + C_OUT*2) * 4)
__global__ void __launch_bounds__(256, 2) gemm2_kernel(const float* __restrict__ W2,
        const float* __restrict__ b2, int n) {
    extern __shared__ char smraw[];
    ull*   Wd   = (ull*)smraw;                              // 64 KB
    float* hs   = (float*)(smraw + C_MID * C_OUT * 8);      // 33.8 KB
    float* s1s  = hs + C_MID * T2_PAD;                      // 64
    float* t1s  = s1s + C_MID;                              // 64
    float* cnts = t1s + C_MID;                              // 128
    float* sW   = cnts + 128;                               // 128
    float* sQ   = sW + C_OUT;                               // 128
    int tid = threadIdx.x;
    int tx = tid & 15, ty = tid >> 4;
    int c0 = tx << 3;          // 8 contiguous cols
    int r0 = ty << 3;          // 8 rows
    int lr = tid & 127;
    int dh = (tid >> 7) << 5;
    for (int i = tid; i < C_MID * C_OUT; i += 256) {
        int c = i & 127;
        float w = W2[i];
        int perm = ((c >> 1) & 3) * 32 + (c >> 3) * 2 + (c & 1);
        Wd[(i >> 7) * 128 + perm] = pack2(w, w);
    }
    if (tid < C_MID) { s1s[tid] = g_s1[tid]; t1s[tid] = g_t1[tid]; }
    if (tid < C_OUT) { sW[tid] = 0.f; sQ[tid] = 0.f; }
    float bc[8];
    {
        float4 ba = *(const float4*)(b2 + c0);
        float4 bb = *(const float4*)(b2 + c0 + 4);
        bc[0]=ba.x; bc[1]=ba.y; bc[2]=ba.z; bc[3]=ba.w;
        bc[4]=bb.x; bc[5]=bb.y; bc[6]=bb.z; bc[7]=bb.w;
    }
    float wsum[8] = {0,0,0,0,0,0,0,0}, wsq[8] = {0,0,0,0,0,0,0,0};
    int ntiles = (n + 127) >> 7;
    uint4 pf[4];
    int tile = blockIdx.x;
    if (tile < ntiles) {
        int gr = (tile << 7) + lr; if (gr >= n) gr = n - 1;
        const uint4* p = (const uint4*)(g_Yh + (size_t)gr * C_MID + dh);
        #pragma unroll
        for (int u = 0; u < 4; u++) pf[u] = p[u];
    }
    for (; tile < ntiles; tile += gridDim.x) {
        int rbase = tile << 7;
        #pragma unroll
        for (int u = 0; u < 4; u++) {       // BN1+relu fused, conflict-free STS
            unsigned hw[4] = { pf[u].x, pf[u].y, pf[u].z, pf[u].w };
            int db = dh + (u << 3);
            #pragma unroll
            for (int q = 0; q < 4; q++) {
                float2 f = __half22float2(*reinterpret_cast<__half2*>(&hw[q]));
                int d = db + (q << 1);
                hs[(d + 0) * T2_PAD + lr] = fmaxf(fmaf(f.x, s1s[d + 0], t1s[d + 0]), 0.f);
                hs[(d + 1) * T2_PAD + lr] = fmaxf(fmaf(f.y, s1s[d + 1], t1s[d + 1]), 0.f);
            }
        }
        if (tid < 128) {
            int gr = rbase + tid;
            cnts[tid] = (gr < n) ? (float)g_cnt[gr] : 0.f;
        }
        __syncthreads();
        int nt = tile + gridDim.x;
        if (nt < ntiles) {
            int gr = (nt << 7) + lr; if (gr >= n) gr = n - 1;
            const uint4* p = (const uint4*)(g_Yh + (size_t)gr * C_MID + dh);
            #pragma unroll
            for (int u = 0; u < 4; u++) pf[u] = p[u];
        }
        ull acc[4][8];
        #pragma unroll
        for (int rp = 0; rp < 4; rp++)
            #pragma unroll
            for (int j = 0; j < 8; j++) acc[rp][j] = pack2(bc[j], bc[j]);
        #pragma unroll 8
        for (int d = 0; d < C_MID; d++) {
            ulonglong2 xA = *(const ulonglong2*)&hs[d * T2_PAD + r0];
            ulonglong2 xB = *(const ulonglong2*)&hs[d * T2_PAD + r0 + 4];
            ull xp[4] = { xA.x, xA.y, xB.x, xB.y };
            ulonglong2 w0 = *(const ulonglong2*)&Wd[d * 128 + 2 * tx];
            ulonglong2 w1 = *(const ulonglong2*)&Wd[d * 128 + 32 + 2 * tx];
            ulonglong2 w2 = *(const ulonglong2*)&Wd[d * 128 + 64 + 2 * tx];
            ulonglong2 w3 = *(const ulonglong2*)&Wd[d * 128 + 96 + 2 * tx];
            ull wd[8] = { w0.x, w0.y, w1.x, w1.y, w2.x, w2.y, w3.x, w3.y };
            #pragma unroll
            for (int rp = 0; rp < 4; rp++)
                #pragma unroll
                for (int j = 0; j < 8; j++)
                    acc[rp][j] = fma2(xp[rp], wd[j], acc[rp][j]);
        }
        #pragma unroll
        for (int rp = 0; rp < 4; rp++) {
            int rA = rbase + r0 + (rp << 1);
            float za[8], zb[8];
            #pragma unroll
            for (int j = 0; j < 8; j++) unpack2(acc[rp][j], za[j], zb[j]);
            if (rA < n) {
                __half2 h0 = __floats2half2_rn(za[0], za[1]);
                __half2 h1 = __floats2half2_rn(za[2], za[3]);
                __half2 h2 = __floats2half2_rn(za[4], za[5]);
                __half2 h3 = __floats2half2_rn(za[6], za[7]);
                uint4 u;
                u.x = *reinterpret_cast<unsigned*>(&h0); u.y = *reinterpret_cast<unsigned*>(&h1);
                u.z = *reinterpret_cast<unsigned*>(&h2); u.w = *reinterpret_cast<unsigned*>(&h3);
                *(uint4*)(g_Zh + (size_t)rA * C_OUT + c0) = u;
                float w = cnts[r0 + (rp << 1)];
                #pragma unroll
                for (int j = 0; j < 8; j++) {
                    wsum[j] = fmaf(w, za[j], wsum[j]);
                    wsq[j]  = fmaf(w, za[j] * za[j], wsq[j]);
                }
            }
            if (rA + 1 < n) {
                __half2 h0 = __floats2half2_rn(zb[0], zb[1]);
                __half2 h1 = __floats2half2_rn(zb[2], zb[3]);
                __half2 h2 = __floats2half2_rn(zb[4], zb[5]);
                __half2 h3 = __floats2half2_rn(zb[6], zb[7]);
                uint4 u;
                u.x = *reinterpret_cast<unsigned*>(&h0); u.y = *reinterpret_cast<unsigned*>(&h1);
                u.z = *reinterpret_cast<unsigned*>(&h2); u.w = *reinterpret_cast<unsigned*>(&h3);
                *(uint4*)(g_Zh + (size_t)(rA + 1) * C_OUT + c0) = u;
                float w = cnts[r0 + (rp << 1) + 1];
                #pragma unroll
                for (int j = 0; j < 8; j++) {
                    wsum[j] = fmaf(w, zb[j], wsum[j]);
                    wsq[j]  = fmaf(w, zb[j] * zb[j], wsq[j]);
                }
            }
        }
        __syncthreads();
    }
    #pragma unroll
    for (int j = 0; j < 8; j++) {
        atomicAdd(&sW[c0 + j], wsum[j]);
        atomicAdd(&sQ[c0 + j], wsq[j]);
    }
    __syncthreads();
    if (tid < C_OUT) {
        atomicAdd(&g_sum2[tid], sW[tid]);
        atomicAdd(&g_sq2[tid],  sQ[tid]);
    }
}

__global__ void finalize2_kernel(const float* __restrict__ g2,
                                 const float* __restrict__ be2, float invN) {
    int c = threadIdx.x;  // 128
    float mu  = g_sum2[c] * invN;
    float var = g_sq2[c] * invN - mu * mu;
    float s = g2[c] * rsqrtf(var + EPS_BN);
    g_s2[c] = s;
    g_t2[c] = be2[c] - mu * s;
}

// ---------------------------------------------------------------------------
// out[i,c] = max_k relu(Zh[idx[i,k],c]*s2[c] + t2[c]).
__global__ void __launch_bounds__(256) gather_max_kernel(const void* __restrict__ idxp,
        float* __restrict__ out, int n, int k) {
    __shared__ int ridx[4][32];
    int tid = threadIdx.x;
    int g  = tid >> 6;      // point slot 0..3
    int c2 = tid & 63;      // half2 channel index
    int i = blockIdx.x * 4 + g;
    bool valid = i < n;
    if (valid && c2 < k) {
        if (g_is64) ridx[g][c2] = (int)((const long long*)idxp)[(size_t)i * k + c2];
        else        ridx[g][c2] = ((const int*)idxp)[(size_t)i * k + c2];
    }
    float2 s = *(const float2*)&g_s2[c2 * 2];
    float2 t = *(const float2*)&g_t2[c2 * 2];
    __syncthreads();
    if (!valid) return;
    float m0 = 0.f, m1 = 0.f;   // relu lower bound
    #pragma unroll 8
    for (int j = 0; j < k; j++) {
        __half2 h = *(const __half2*)(g_Zh + (size_t)ridx[g][j] * C_OUT + c2 * 2);
        float2 z = __half22float2(h);
        m0 = fmaxf(m0, fmaf(z.x, s.x, t.x));
        m1 = fmaxf(m1, fmaf(z.y, s.y, t.y));
    }
    *(float2*)(out + (size_t)i * C_OUT + c2 * 2) = make_float2(m0, m1);
}

// ---------------------------------------------------------------------------
extern "C" void kernel_launch(void* const* d_in, const int* in_sizes, int n_in,
                              void* d_out, int out_size) {
    const float* feat = (const float*)d_in[0];
    const void*  idx  = d_in[1];
    const float* W1   = (const float*)d_in[2];
    const float* b1   = (const float*)d_in[3];
    const float* g1   = (const float*)d_in[4];
    const float* be1  = (const float*)d_in[5];
    const float* W2   = (const float*)d_in[6];
    const float* b2   = (const float*)d_in[7];
    const float* g2   = (const float*)d_in[8];
    const float* be2  = (const float*)d_in[9];
    float* out = (float*)d_out;

    int n = in_sizes[0] / C_IN;       // 100000
    int k = in_sizes[1] / n;          // 16
    int total = n * k;                // 1.6M
    float invN = 1.0f / (float)total;

    static bool attr_done = false;
    if (!attr_done) {
        cudaFuncSetAttribute(gemm1_kernel, cudaFuncAttributeMaxDynamicSharedMemorySize,
                             SMEM1_BYTES);
        cudaFuncSetAttribute(gemm2_kernel, cudaFuncAttributeMaxDynamicSharedMemorySize,
                             SMEM2_BYTES);
        attr_done = true;
    }

    zero_kernel<<<(n + 255) / 256, 256>>>(n);
    detect_kernel<<<1, 1024>>>(idx);
    hist_kernel<<<(total + 255) / 256, 256>>>(idx, total);
    gemm1_kernel<<<296, 256, SMEM1_BYTES>>>(feat, W1, b1, n);
    finalize1_kernel<<<1, C_MID>>>(g1, be1, invN);
    gemm2_kernel<<<296, 256, SMEM2_BYTES>>>(W2, b2, n);
    finalize2_kernel<<<1, C_OUT>>>(g2, be2, invN);
    gather_max_kernel<<<(n + 3) / 4, 256>>>(idx, out, n, k);
}

// round 13
// speedup vs baseline: 1.0004x; 1.0004x over previous
#include <cuda_runtime.h>
#include <cuda_fp16.h>

#define C_IN  64
#define C_MID 64
#define C_OUT 128
#define N_MAX 100000
#define EPS_BN 1e-5f

typedef unsigned long long ull;

// ---- scratch (device globals; no allocations allowed) ----
__device__ int    g_cnt[N_MAX];
__device__ __align__(16) __half g_Yh[N_MAX * C_MID];    // pre-BN layer-1 activations (fp16)
__device__ __align__(16) __half g_Zh[N_MAX * C_OUT];    // pre-BN layer-2 activations (fp16)
__device__ __align__(16) float g_sum1[C_MID], g_sq1[C_MID];
__device__ __align__(16) float g_sum2[C_OUT], g_sq2[C_OUT];
__device__ __align__(16) float g_s1[C_MID],  g_t1[C_MID];
__device__ __align__(16) float g_s2[C_OUT],  g_t2[C_OUT];
__device__ int   g_is64;

// ---- packed fp32x2 helpers (Blackwell FFMA2; ptxas won't auto-fuse) ----
__device__ __forceinline__ ull pack2(float lo, float hi) {
    ull r; asm("mov.b64 %0, {%1, %2};" : "=l"(r) : "f"(lo), "f"(hi)); return r;
}
__device__ __forceinline__ void unpack2(ull v, float& lo, float& hi) {
    asm("mov.b64 {%0, %1}, %2;" : "=f"(lo), "=f"(hi) : "l"(v));
}
__device__ __forceinline__ ull fma2(ull a, ull b, ull c) {
    ull d; asm("fma.rn.f32x2 %0, %1, %2, %3;" : "=l"(d) : "l"(a), "l"(b), "l"(c)); return d;
}

// ---------------------------------------------------------------------------
__global__ void zero_kernel(int n) {
    int i = blockIdx.x * blockDim.x + threadIdx.x;
    if (i < n) g_cnt[i] = 0;
    if (i < C_MID) { g_sum1[i] = 0.f; g_sq1[i] = 0.f; }
    if (i < C_OUT) { g_sum2[i] = 0.f; g_sq2[i] = 0.f; }
}

// int64 little-endian => odd int32 words (high halves) all zero (values < n).
__global__ void detect_kernel(const void* idxp) {
    const int* w = (const int*)idxp;
    int t = threadIdx.x;
    int any = (w[2 * t + 1] != 0) ? 1 : 0;
    int r = __syncthreads_or(any);
    if (t == 0) g_is64 = (r == 0) ? 1 : 0;
}

__global__ void hist_kernel(const void* idxp, int total) {
    int i = blockIdx.x * blockDim.x + threadIdx.x;
    if (i >= total) return;
    int v;
    if (g_is64) v = (int)((const long long*)idxp)[i];
    else        v = ((const int*)idxp)[i];
    atomicAdd(&g_cnt[v], 1);
}

// ---------------------------------------------------------------------------
// GEMM1: Y = feat @ W1 + b1 (Y stored fp16), plus count-weighted stats.
// Block tile 128r x 64c. Thread: 8 rows (4 f32x2 row-pairs) x 4 cols.
// W pre-duplicated+permuted in shared so each LDS.128 is 16B-lane-stride
// (conflict-free) and the inner loop is pure LDS + FFMA2.
// perm(c) = ((c>>1)&1)*32 + (c>>2)*2 + (c&1); thread tx owns cols 4tx..4tx+3.
#define T1_PAD 132
#define SMEM1_BYTES (C_IN * C_MID * 8 + C_IN * T1_PAD * 4 + 128 * 4 + C_MID * 8)
__global__ void __launch_bounds__(256, 2) gemm1_kernel(const float* __restrict__ feat,
        const float* __restrict__ W1, const float* __restrict__ b1, int n) {
    extern __shared__ char smraw[];
    ull*   Wd   = (ull*)smraw;                              // 32 KB
    float* xs   = (float*)(smraw + C_IN * C_MID * 8);       // 33.8 KB
    float* cnts = xs + C_IN * T1_PAD;                       // 128
    float* sW   = cnts + 128;                               // 64
    float* sQ   = sW + C_MID;                               // 64
    int tid = threadIdx.x;
    int tx = tid & 15, ty = tid >> 4;
    int c0 = tx << 2;          // 4 contiguous cols
    int r0 = ty << 3;          // 8 rows
    int lr = tid & 127;        // loader row
    int dh = (tid >> 7) << 5;  // loader d-half (0/32)
    for (int i = tid; i < C_IN * C_MID; i += 256) {
        int c = i & 63;
        float w = W1[i];
        int perm = ((c >> 1) & 1) * 32 + (c >> 2) * 2 + (c & 1);
        Wd[(i >> 6) * 64 + perm] = pack2(w, w);
    }
    if (tid < C_MID) { sW[tid] = 0.f; sQ[tid] = 0.f; }
    float4 bv = *(const float4*)(b1 + c0);
    float wsum[4] = {0,0,0,0}, wsq[4] = {0,0,0,0};
    int ntiles = (n + 127) >> 7;
    float4 pf[8];
    int tile = blockIdx.x;
    if (tile < ntiles) {
        int gr = (tile << 7) + lr; if (gr >= n) gr = n - 1;
        const float4* p = (const float4*)(feat + (size_t)gr * C_IN + dh);
        #pragma unroll
        for (int u = 0; u < 8; u++) pf[u] = p[u];
    }
    for (; tile < ntiles; tile += gridDim.x) {
        int rbase = tile << 7;
        #pragma unroll
        for (int u = 0; u < 8; u++) {       // conflict-free transpose STS
            int d = dh + (u << 2);
            xs[(d + 0) * T1_PAD + lr] = pf[u].x;
            xs[(d + 1) * T1_PAD + lr] = pf[u].y;
            xs[(d + 2) * T1_PAD + lr] = pf[u].z;
            xs[(d + 3) * T1_PAD + lr] = pf[u].w;
        }
        if (tid < 128) {
            int gr = rbase + tid;
            cnts[tid] = (gr < n) ? (float)g_cnt[gr] : 0.f;
        }
        __syncthreads();
        int nt = tile + gridDim.x;          // prefetch next tile behind FMA
        if (nt < ntiles) {
            int gr = (nt << 7) + lr; if (gr >= n) gr = n - 1;
            const float4* p = (const float4*)(feat + (size_t)gr * C_IN + dh);
            #pragma unroll
            for (int u = 0; u < 8; u++) pf[u] = p[u];
        }
        ull acc[4][4];
        #pragma unroll
        for (int rp = 0; rp < 4; rp++) {
            acc[rp][0] = pack2(bv.x, bv.x); acc[rp][1] = pack2(bv.y, bv.y);
            acc[rp][2] = pack2(bv.z, bv.z); acc[rp][3] = pack2(bv.w, bv.w);
        }
        #pragma unroll 8
        for (int d = 0; d < C_IN; d++) {
            ulonglong2 xA = *(const ulonglong2*)&xs[d * T1_PAD + r0];
            ulonglong2 xB = *(const ulonglong2*)&xs[d * T1_PAD + r0 + 4];
            ulonglong2 wA = *(const ulonglong2*)&Wd[d * 64 + 2 * tx];       // cols c0,c0+1
            ulonglong2 wB = *(const ulonglong2*)&Wd[d * 64 + 32 + 2 * tx];  // cols c0+2,c0+3
            acc[0][0] = fma2(xA.x, wA.x, acc[0][0]); acc[0][1] = fma2(xA.x, wA.y, acc[0][1]);
            acc[0][2] = fma2(xA.x, wB.x, acc[0][2]); acc[0][3] = fma2(xA.x, wB.y, acc[0][3]);
            acc[1][0] = fma2(xA.y, wA.x, acc[1][0]); acc[1][1] = fma2(xA.y, wA.y, acc[1][1]);
            acc[1][2] = fma2(xA.y, wB.x, acc[1][2]); acc[1][3] = fma2(xA.y, wB.y, acc[1][3]);
            acc[2][0] = fma2(xB.x, wA.x, acc[2][0]); acc[2][1] = fma2(xB.x, wA.y, acc[2][1]);
            acc[2][2] = fma2(xB.x, wB.x, acc[2][2]); acc[2][3] = fma2(xB.x, wB.y, acc[2][3]);
            acc[3][0] = fma2(xB.y, wA.x, acc[3][0]); acc[3][1] = fma2(xB.y, wA.y, acc[3][1]);
            acc[3][2] = fma2(xB.y, wB.x, acc[3][2]); acc[3][3] = fma2(xB.y, wB.y, acc[3][3]);
        }
        #pragma unroll
        for (int rp = 0; rp < 4; rp++) {
            int rA = rbase + r0 + (rp << 1);
            float ya[4], yb[4];
            #pragma unroll
            for (int j = 0; j < 4; j++) unpack2(acc[rp][j], ya[j], yb[j]);
            if (rA < n) {
                __half2 h0 = __floats2half2_rn(ya[0], ya[1]);
                __half2 h1 = __floats2half2_rn(ya[2], ya[3]);
                uint2 u; u.x = *reinterpret_cast<unsigned*>(&h0);
                u.y = *reinterpret_cast<unsigned*>(&h1);
                *(uint2*)(g_Yh + (size_t)rA * C_MID + c0) = u;
                float w = cnts[r0 + (rp << 1)];
                #pragma unroll
                for (int j = 0; j < 4; j++) {
                    wsum[j] = fmaf(w, ya[j], wsum[j]);
                    wsq[j]  = fmaf(w, ya[j] * ya[j], wsq[j]);
                }
            }
            if (rA + 1 < n) {
                __half2 h0 = __floats2half2_rn(yb[0], yb[1]);
                __half2 h1 = __floats2half2_rn(yb[2], yb[3]);
                uint2 u; u.x = *reinterpret_cast<unsigned*>(&h0);
                u.y = *reinterpret_cast<unsigned*>(&h1);
                *(uint2*)(g_Yh + (size_t)(rA + 1) * C_MID + c0) = u;
                float w = cnts[r0 + (rp << 1) + 1];
                #pragma unroll
                for (int j = 0; j < 4; j++) {
                    wsum[j] = fmaf(w, yb[j], wsum[j]);
                    wsq[j]  = fmaf(w, yb[j] * yb[j], wsq[j]);
                }
            }
        }
        __syncthreads();
    }
    #pragma unroll
    for (int j = 0; j < 4; j++) {
        atomicAdd(&sW[c0 + j], wsum[j]);
        atomicAdd(&sQ[c0 + j], wsq[j]);
    }
    __syncthreads();
    if (tid < C_MID) {
        atomicAdd(&g_sum1[tid], sW[tid]);
        atomicAdd(&g_sq1[tid],  sQ[tid]);
    }
}

__global__ void finalize1_kernel(const float* __restrict__ g1,
                                 const float* __restrict__ be1, float invN) {
    int c = threadIdx.x;  // 64
    float mu  = g_sum1[c] * invN;
    float var = g_sq1[c] * invN - mu * mu;
    float s = g1[c] * rsqrtf(var + EPS_BN);
    g_s1[c] = s;
    g_t1[c] = be1[c] - mu * s;
}

// ---------------------------------------------------------------------------
// GEMM2: H = relu(Yh*s1+t1) fused into loader; Z = H @ W2 + b2; Z stored fp16.
// Block tile 128r x 128c. Thread: 8 rows (4 pairs) x 8 cols, dup-permuted W.
// perm2(c) = ((c>>1)&3)*32 + (c>>3)*2 + (c&1); thread tx owns cols 8tx..8tx+7.
#define T2_PAD 132
#define SMEM2_BYTES (C_MID * C_OUT * 8 + C_MID * T2_PAD * 4 + (C_MID*2 + 128 + C_OUT*2) * 4)
__global__ void __launch_bounds__(256, 2) gemm2_kernel(const float* __restrict__ W2,
        const float* __restrict__ b2, int n) {
    extern __shared__ char smraw[];
    ull*   Wd   = (ull*)smraw;                              // 64 KB
    float* hs   = (float*)(smraw + C_MID * C_OUT * 8);      // 33.8 KB
    float* s1s  = hs + C_MID * T2_PAD;                      // 64
    float* t1s  = s1s + C_MID;                              // 64
    float* cnts = t1s + C_MID;                              // 128
    float* sW   = cnts + 128;                               // 128
    float* sQ   = sW + C_OUT;                               // 128
    int tid = threadIdx.x;
    int tx = tid & 15, ty = tid >> 4;
    int c0 = tx << 3;          // 8 contiguous cols
    int r0 = ty << 3;          // 8 rows
    int lr = tid & 127;
    int dh = (tid >> 7) << 5;
    for (int i = tid; i < C_MID * C_OUT; i += 256) {
        int c = i & 127;
        float w = W2[i];
        int perm = ((c >> 1) & 3) * 32 + (c >> 3) * 2 + (c & 1);
        Wd[(i >> 7) * 128 + perm] = pack2(w, w);
    }
    if (tid < C_MID) { s1s[tid] = g_s1[tid]; t1s[tid] = g_t1[tid]; }
    if (tid < C_OUT) { sW[tid] = 0.f; sQ[tid] = 0.f; }
    float bc[8];
    {
        float4 ba = *(const float4*)(b2 + c0);
        float4 bb = *(const float4*)(b2 + c0 + 4);
        bc[0]=ba.x; bc[1]=ba.y; bc[2]=ba.z; bc[3]=ba.w;
        bc[4]=bb.x; bc[5]=bb.y; bc[6]=bb.z; bc[7]=bb.w;
    }
    float wsum[8] = {0,0,0,0,0,0,0,0}, wsq[8] = {0,0,0,0,0,0,0,0};
    int ntiles = (n + 127) >> 7;
    uint4 pf[4];
    int tile = blockIdx.x;
    if (tile < ntiles) {
        int gr = (tile << 7) + lr; if (gr >= n) gr = n - 1;
        const uint4* p = (const uint4*)(g_Yh + (size_t)gr * C_MID + dh);
        #pragma unroll
        for (int u = 0; u < 4; u++) pf[u] = p[u];
    }
    for (; tile < ntiles; tile += gridDim.x) {
        int rbase = tile << 7;
        #pragma unroll
        for (int u = 0; u < 4; u++) {       // BN1+relu fused, conflict-free STS
            unsigned hw[4] = { pf[u].x, pf[u].y, pf[u].z, pf[u].w };
            int db = dh + (u << 3);
            #pragma unroll
            for (int q = 0; q < 4; q++) {
                float2 f = __half22float2(*reinterpret_cast<__half2*>(&hw[q]));
                int d = db + (q << 1);
                hs[(d + 0) * T2_PAD + lr] = fmaxf(fmaf(f.x, s1s[d + 0], t1s[d + 0]), 0.f);
                hs[(d + 1) * T2_PAD + lr] = fmaxf(fmaf(f.y, s1s[d + 1], t1s[d + 1]), 0.f);
            }
        }
        if (tid < 128) {
            int gr = rbase + tid;
            cnts[tid] = (gr < n) ? (float)g_cnt[gr] : 0.f;
        }
        __syncthreads();
        int nt = tile + gridDim.x;
        if (nt < ntiles) {
            int gr = (nt << 7) + lr; if (gr >= n) gr = n - 1;
            const uint4* p = (const uint4*)(g_Yh + (size_t)gr * C_MID + dh);
            #pragma unroll
            for (int u = 0; u < 4; u++) pf[u] = p[u];
        }
        ull acc[4][8];
        #pragma unroll
        for (int rp = 0; rp < 4; rp++)
            #pragma unroll
            for (int j = 0; j < 8; j++) acc[rp][j] = pack2(bc[j], bc[j]);
        #pragma unroll 8
        for (int d = 0; d < C_MID; d++) {
            ulonglong2 xA = *(const ulonglong2*)&hs[d * T2_PAD + r0];
            ulonglong2 xB = *(const ulonglong2*)&hs[d * T2_PAD + r0 + 4];
            ull xp[4] = { xA.x, xA.y, xB.x, xB.y };
            ulonglong2 w0 = *(const ulonglong2*)&Wd[d * 128 + 2 * tx];
            ulonglong2 w1 = *(const ulonglong2*)&Wd[d * 128 + 32 + 2 * tx];
            ulonglong2 w2 = *(const ulonglong2*)&Wd[d * 128 + 64 + 2 * tx];
            ulonglong2 w3 = *(const ulonglong2*)&Wd[d * 128 + 96 + 2 * tx];
            ull wd[8] = { w0.x, w0.y, w1.x, w1.y, w2.x, w2.y, w3.x, w3.y };
            #pragma unroll
            for (int rp = 0; rp < 4; rp++)
                #pragma unroll
                for (int j = 0; j < 8; j++)
                    acc[rp][j] = fma2(xp[rp], wd[j], acc[rp][j]);
        }
        #pragma unroll
        for (int rp = 0; rp < 4; rp++) {
            int rA = rbase + r0 + (rp << 1);
            float za[8], zb[8];
            #pragma unroll
            for (int j = 0; j < 8; j++) unpack2(acc[rp][j], za[j], zb[j]);
            if (rA < n) {
                __half2 h0 = __floats2half2_rn(za[0], za[1]);
                __half2 h1 = __floats2half2_rn(za[2], za[3]);
                __half2 h2 = __floats2half2_rn(za[4], za[5]);
                __half2 h3 = __floats2half2_rn(za[6], za[7]);
                uint4 u;
                u.x = *reinterpret_cast<unsigned*>(&h0); u.y = *reinterpret_cast<unsigned*>(&h1);
                u.z = *reinterpret_cast<unsigned*>(&h2); u.w = *reinterpret_cast<unsigned*>(&h3);
                *(uint4*)(g_Zh + (size_t)rA * C_OUT + c0) = u;
                float w = cnts[r0 + (rp << 1)];
                #pragma unroll
                for (int j = 0; j < 8; j++) {
                    wsum[j] = fmaf(w, za[j], wsum[j]);
                    wsq[j]  = fmaf(w, za[j] * za[j], wsq[j]);
                }
            }
            if (rA + 1 < n) {
                __half2 h0 = __floats2half2_rn(zb[0], zb[1]);
                __half2 h1 = __floats2half2_rn(zb[2], zb[3]);
                __half2 h2 = __floats2half2_rn(zb[4], zb[5]);
                __half2 h3 = __floats2half2_rn(zb[6], zb[7]);
                uint4 u;
                u.x = *reinterpret_cast<unsigned*>(&h0); u.y = *reinterpret_cast<unsigned*>(&h1);
                u.z = *reinterpret_cast<unsigned*>(&h2); u.w = *reinterpret_cast<unsigned*>(&h3);
                *(uint4*)(g_Zh + (size_t)(rA + 1) * C_OUT + c0) = u;
                float w = cnts[r0 + (rp << 1) + 1];
                #pragma unroll
                for (int j = 0; j < 8; j++) {
                    wsum[j] = fmaf(w, zb[j], wsum[j]);
                    wsq[j]  = fmaf(w, zb[j] * zb[j], wsq[j]);
                }
            }
        }
        __syncthreads();
    }
    #pragma unroll
    for (int j = 0; j < 8; j++) {
        atomicAdd(&sW[c0 + j], wsum[j]);
        atomicAdd(&sQ[c0 + j], wsq[j]);
    }
    __syncthreads();
    if (tid < C_OUT) {
        atomicAdd(&g_sum2[tid], sW[tid]);
        atomicAdd(&g_sq2[tid],  sQ[tid]);
    }
}

__global__ void finalize2_kernel(const float* __restrict__ g2,
                                 const float* __restrict__ be2, float invN) {
    int c = threadIdx.x;  // 128
    float mu  = g_sum2[c] * invN;
    float var = g_sq2[c] * invN - mu * mu;
    float s = g2[c] * rsqrtf(var + EPS_BN);
    g_s2[c] = s;
    g_t2[c] = be2[c] - mu * s;
}

// ---------------------------------------------------------------------------
// out[i,c] = max_k relu(Zh[idx[i,k],c]*s2[c] + t2[c]).
__global__ void __launch_bounds__(256) gather_max_kernel(const void* __restrict__ idxp,
        float* __restrict__ out, int n, int k) {
    __shared__ int ridx[4][32];
    int tid = threadIdx.x;
    int g  = tid >> 6;      // point slot 0..3
    int c2 = tid & 63;      // half2 channel index
    int i = blockIdx.x * 4 + g;
    bool valid = i < n;
    if (valid && c2 < k) {
        if (g_is64) ridx[g][c2] = (int)((const long long*)idxp)[(size_t)i * k + c2];
        else        ridx[g][c2] = ((const int*)idxp)[(size_t)i * k + c2];
    }
    float2 s = *(const float2*)&g_s2[c2 * 2];
    float2 t = *(const float2*)&g_t2[c2 * 2];
    __syncthreads();
    if (!valid) return;
    float m0 = 0.f, m1 = 0.f;   // relu lower bound
    #pragma unroll 8
    for (int j = 0; j < k; j++) {
        __half2 h = *(const __half2*)(g_Zh + (size_t)ridx[g][j] * C_OUT + c2 * 2);
        float2 z = __half22float2(h);
        m0 = fmaxf(m0, fmaf(z.x, s.x, t.x));
        m1 = fmaxf(m1, fmaf(z.y, s.y, t.y));
    }
    *(float2*)(out + (size_t)i * C_OUT + c2 * 2) = make_float2(m0, m1);
}

// ---------------------------------------------------------------------------
extern "C" void kernel_launch(void* const* d_in, const int* in_sizes, int n_in,
                              void* d_out, int out_size) {
    const float* feat = (const float*)d_in[0];
    const void*  idx  = d_in[1];
    const float* W1   = (const float*)d_in[2];
    const float* b1   = (const float*)d_in[3];
    const float* g1   = (const float*)d_in[4];
    const float* be1  = (const float*)d_in[5];
    const float* W2   = (const float*)d_in[6];
    const float* b2   = (const float*)d_in[7];
    const float* g2   = (const float*)d_in[8];
    const float* be2  = (const float*)d_in[9];
    float* out = (float*)d_out;

    int n = in_sizes[0] / C_IN;       // 100000
    int k = in_sizes[1] / n;          // 16
    int total = n * k;                // 1.6M
    float invN = 1.0f / (float)total;

    static bool attr_done = false;
    if (!attr_done) {
        cudaFuncSetAttribute(gemm1_kernel, cudaFuncAttributeMaxDynamicSharedMemorySize,
                             SMEM1_BYTES);
        cudaFuncSetAttribute(gemm2_kernel, cudaFuncAttributeMaxDynamicSharedMemorySize,
                             SMEM2_BYTES);
        attr_done = true;
    }

    zero_kernel<<<(n + 255) / 256, 256>>>(n);
    detect_kernel<<<1, 1024>>>(idx);
    hist_kernel<<<(total + 255) / 256, 256>>>(idx, total);
    gemm1_kernel<<<296, 256, SMEM1_BYTES>>>(feat, W1, b1, n);
    finalize1_kernel<<<1, C_MID>>>(g1, be1, invN);
    gemm2_kernel<<<296, 256, SMEM2_BYTES>>>(W2, b2, n);
    finalize2_kernel<<<1, C_OUT>>>(g2, be2, invN);
    gather_max_kernel<<<(n + 3) / 4, 256>>>(idx, out, n, k);
}

// round 15
// speedup vs baseline: 1.0006x; 1.0002x over previous
#include <cuda_runtime.h>
#include <cuda_fp16.h>

#define C_IN  64
#define C_MID 64
#define C_OUT 128
#define N_MAX 100000
#define EPS_BN 1e-5f

typedef unsigned long long ull;

// ---- scratch (device globals; no allocations allowed) ----
__device__ int    g_cnt[N_MAX];
__device__ __align__(16) __half g_Yh[N_MAX * C_MID];    // pre-BN layer-1 activations (fp16)
__device__ __align__(16) __half g_Zh[N_MAX * C_OUT];    // pre-BN layer-2 activations (fp16)
__device__ __align__(16) float g_sum1[C_MID], g_sq1[C_MID];
__device__ __align__(16) float g_sum2[C_OUT], g_sq2[C_OUT];
__device__ __align__(16) float g_s1[C_MID],  g_t1[C_MID];
__device__ __align__(16) float g_s2[C_OUT],  g_t2[C_OUT];
__device__ int   g_is64;

// ---- packed fp32x2 helpers (Blackwell FFMA2; ptxas won't auto-fuse) ----
__device__ __forceinline__ ull pack2(float lo, float hi) {
    ull r; asm("mov.b64 %0, {%1, %2};" : "=l"(r) : "f"(lo), "f"(hi)); return r;
}
__device__ __forceinline__ void unpack2(ull v, float& lo, float& hi) {
    asm("mov.b64 {%0, %1}, %2;" : "=f"(lo), "=f"(hi) : "l"(v));
}
__device__ __forceinline__ ull fma2(ull a, ull b, ull c) {
    ull d; asm("fma.rn.f32x2 %0, %1, %2, %3;" : "=l"(d) : "l"(a), "l"(b), "l"(c)); return d;
}

// ---------------------------------------------------------------------------
__global__ void zero_kernel(int n) {
    int i = blockIdx.x * blockDim.x + threadIdx.x;
    if (i < n) g_cnt[i] = 0;
    if (i < C_MID) { g_sum1[i] = 0.f; g_sq1[i] = 0.f; }
    if (i < C_OUT) { g_sum2[i] = 0.f; g_sq2[i] = 0.f; }
}

// int64 little-endian => odd int32 words (high halves) all zero (values < n).
__global__ void detect_kernel(const void* idxp) {
    const int* w = (const int*)idxp;
    int t = threadIdx.x;
    int any = (w[2 * t + 1] != 0) ? 1 : 0;
    int r = __syncthreads_or(any);
    if (t == 0) g_is64 = (r == 0) ? 1 : 0;
}

__global__ void hist_kernel(const void* idxp, int total) {
    int i = blockIdx.x * blockDim.x + threadIdx.x;
    if (i >= total) return;
    int v;
    if (g_is64) v = (int)((const long long*)idxp)[i];
    else        v = ((const int*)idxp)[i];
    atomicAdd(&g_cnt[v], 1);
}

// ---------------------------------------------------------------------------
// GEMM1: Y = feat @ W1 + b1 (Y stored fp16), plus count-weighted stats.
// Block tile 128r x 64c. Thread: 8 rows (4 f32x2 row-pairs) x 4 cols.
// W pre-duplicated+permuted in shared so each LDS.128 is 16B-lane-stride
// (conflict-free) and the inner loop is pure LDS + FFMA2.
// perm(c) = ((c>>1)&1)*32 + (c>>2)*2 + (c&1); thread tx owns cols 4tx..4tx+3.
#define T1_PAD 132
#define SMEM1_BYTES (C_IN * C_MID * 8 + C_IN * T1_PAD * 4 + 128 * 4 + C_MID * 8)
__global__ void __launch_bounds__(256, 2) gemm1_kernel(const float* __restrict__ feat,
        const float* __restrict__ W1, const float* __restrict__ b1, int n) {
    extern __shared__ char smraw[];
    ull*   Wd   = (ull*)smraw;                              // 32 KB
    float* xs   = (float*)(smraw + C_IN * C_MID * 8);       // 33.8 KB
    float* cnts = xs + C_IN * T1_PAD;                       // 128
    float* sW   = cnts + 128;                               // 64
    float* sQ   = sW + C_MID;                               // 64
    int tid = threadIdx.x;
    int tx = tid & 15, ty = tid >> 4;
    int c0 = tx << 2;          // 4 contiguous cols
    int r0 = ty << 3;          // 8 rows
    int lr = tid & 127;        // loader row
    int dh = (tid >> 7) << 5;  // loader d-half (0/32)
    for (int i = tid; i < C_IN * C_MID; i += 256) {
        int c = i & 63;
        float w = W1[i];
        int perm = ((c >> 1) & 1) * 32 + (c >> 2) * 2 + (c & 1);
        Wd[(i >> 6) * 64 + perm] = pack2(w, w);
    }
    if (tid < C_MID) { sW[tid] = 0.f; sQ[tid] = 0.f; }
    float4 bv = *(const float4*)(b1 + c0);
    float wsum[4] = {0,0,0,0}, wsq[4] = {0,0,0,0};
    int ntiles = (n + 127) >> 7;
    float4 pf[8];
    int tile = blockIdx.x;
    if (tile < ntiles) {
        int gr = (tile << 7) + lr; if (gr >= n) gr = n - 1;
        const float4* p = (const float4*)(feat + (size_t)gr * C_IN + dh);
        #pragma unroll
        for (int u = 0; u < 8; u++) pf[u] = p[u];
    }
    for (; tile < ntiles; tile += gridDim.x) {
        int rbase = tile << 7;
        #pragma unroll
        for (int u = 0; u < 8; u++) {       // conflict-free transpose STS
            int d = dh + (u << 2);
            xs[(d + 0) * T1_PAD + lr] = pf[u].x;
            xs[(d + 1) * T1_PAD + lr] = pf[u].y;
            xs[(d + 2) * T1_PAD + lr] = pf[u].z;
            xs[(d + 3) * T1_PAD + lr] = pf[u].w;
        }
        if (tid < 128) {
            int gr = rbase + tid;
            cnts[tid] = (gr < n) ? (float)g_cnt[gr] : 0.f;
        }
        __syncthreads();
        int nt = tile + gridDim.x;          // prefetch next tile behind FMA
        if (nt < ntiles) {
            int gr = (nt << 7) + lr; if (gr >= n) gr = n - 1;
            const float4* p = (const float4*)(feat + (size_t)gr * C_IN + dh);
            #pragma unroll
            for (int u = 0; u < 8; u++) pf[u] = p[u];
        }
        ull acc[4][4];
        #pragma unroll
        for (int rp = 0; rp < 4; rp++) {
            acc[rp][0] = pack2(bv.x, bv.x); acc[rp][1] = pack2(bv.y, bv.y);
            acc[rp][2] = pack2(bv.z, bv.z); acc[rp][3] = pack2(bv.w, bv.w);
        }
        #pragma unroll 8
        for (int d = 0; d < C_IN; d++) {
            ulonglong2 xA = *(const ulonglong2*)&xs[d * T1_PAD + r0];
            ulonglong2 xB = *(const ulonglong2*)&xs[d * T1_PAD + r0 + 4];
            ulonglong2 wA = *(const ulonglong2*)&Wd[d * 64 + 2 * tx];       // cols c0,c0+1
            ulonglong2 wB = *(const ulonglong2*)&Wd[d * 64 + 32 + 2 * tx];  // cols c0+2,c0+3
            acc[0][0] = fma2(xA.x, wA.x, acc[0][0]); acc[0][1] = fma2(xA.x, wA.y, acc[0][1]);
            acc[0][2] = fma2(xA.x, wB.x, acc[0][2]); acc[0][3] = fma2(xA.x, wB.y, acc[0][3]);
            acc[1][0] = fma2(xA.y, wA.x, acc[1][0]); acc[1][1] = fma2(xA.y, wA.y, acc[1][1]);
            acc[1][2] = fma2(xA.y, wB.x, acc[1][2]); acc[1][3] = fma2(xA.y, wB.y, acc[1][3]);
            acc[2][0] = fma2(xB.x, wA.x, acc[2][0]); acc[2][1] = fma2(xB.x, wA.y, acc[2][1]);
            acc[2][2] = fma2(xB.x, wB.x, acc[2][2]); acc[2][3] = fma2(xB.x, wB.y, acc[2][3]);
            acc[3][0] = fma2(xB.y, wA.x, acc[3][0]); acc[3][1] = fma2(xB.y, wA.y, acc[3][1]);
            acc[3][2] = fma2(xB.y, wB.x, acc[3][2]); acc[3][3] = fma2(xB.y, wB.y, acc[3][3]);
        }
        #pragma unroll
        for (int rp = 0; rp < 4; rp++) {
            int rA = rbase + r0 + (rp << 1);
            float ya[4], yb[4];
            #pragma unroll
            for (int j = 0; j < 4; j++) unpack2(acc[rp][j], ya[j], yb[j]);
            if (rA < n) {
                __half2 h0 = __floats2half2_rn(ya[0], ya[1]);
                __half2 h1 = __floats2half2_rn(ya[2], ya[3]);
                uint2 u; u.x = *reinterpret_cast<unsigned*>(&h0);
                u.y = *reinterpret_cast<unsigned*>(&h1);
                *(uint2*)(g_Yh + (size_t)rA * C_MID + c0) = u;
                float w = cnts[r0 + (rp << 1)];
                #pragma unroll
                for (int j = 0; j < 4; j++) {
                    wsum[j] = fmaf(w, ya[j], wsum[j]);
                    wsq[j]  = fmaf(w, ya[j] * ya[j], wsq[j]);
                }
            }
            if (rA + 1 < n) {
                __half2 h0 = __floats2half2_rn(yb[0], yb[1]);
                __half2 h1 = __floats2half2_rn(yb[2], yb[3]);
                uint2 u; u.x = *reinterpret_cast<unsigned*>(&h0);
                u.y = *reinterpret_cast<unsigned*>(&h1);
                *(uint2*)(g_Yh + (size_t)(rA + 1) * C_MID + c0) = u;
                float w = cnts[r0 + (rp << 1) + 1];
                #pragma unroll
                for (int j = 0; j < 4; j++) {
                    wsum[j] = fmaf(w, yb[j], wsum[j]);
                    wsq[j]  = fmaf(w, yb[j] * yb[j], wsq[j]);
                }
            }
        }
        __syncthreads();
    }
    #pragma unroll
    for (int j = 0; j < 4; j++) {
        atomicAdd(&sW[c0 + j], wsum[j]);
        atomicAdd(&sQ[c0 + j], wsq[j]);
    }
    __syncthreads();
    if (tid < C_MID) {
        atomicAdd(&g_sum1[tid], sW[tid]);
        atomicAdd(&g_sq1[tid],  sQ[tid]);
    }
}

__global__ void finalize1_kernel(const float* __restrict__ g1,
                                 const float* __restrict__ be1, float invN) {
    int c = threadIdx.x;  // 64
    float mu  = g_sum1[c] * invN;
    float var = g_sq1[c] * invN - mu * mu;
    float s = g1[c] * rsqrtf(var + EPS_BN);
    g_s1[c] = s;
    g_t1[c] = be1[c] - mu * s;
}

// ---------------------------------------------------------------------------
// GEMM2: H = relu(Yh*s1+t1) fused into loader; Z = H @ W2 + b2; Z stored fp16.
// Block tile 128r x 128c. Thread: 8 rows (4 pairs) x 8 cols, dup-permuted W.
// perm2(c) = ((c>>1)&3)*32 + (c>>3)*2 + (c&1); thread tx owns cols 8tx..8tx+7.
#define T2_PAD 132
#define SMEM2_BYTES (C_MID * C_OUT * 8 + C_MID * T2_PAD * 4 + (C_MID*2 + 128 + C_OUT*2) * 4)
__global__ void __launch_bounds__(256, 2) gemm2_kernel(const float* __restrict__ W2,
        const float* __restrict__ b2, int n) {
    extern __shared__ char smraw[];
    ull*   Wd   = (ull*)smraw;                              // 64 KB
    float* hs   = (float*)(smraw + C_MID * C_OUT * 8);      // 33.8 KB
    float* s1s  = hs + C_MID * T2_PAD;                      // 64
    float* t1s  = s1s + C_MID;                              // 64
    float* cnts = t1s + C_MID;                              // 128
    float* sW   = cnts + 128;                               // 128
    float* sQ   = sW + C_OUT;                               // 128
    int tid = threadIdx.x;
    int tx = tid & 15, ty = tid >> 4;
    int c0 = tx << 3;          // 8 contiguous cols
    int r0 = ty << 3;          // 8 rows
    int lr = tid & 127;
    int dh = (tid >> 7) << 5;
    for (int i = tid; i < C_MID * C_OUT; i += 256) {
        int c = i & 127;
        float w = W2[i];
        int perm = ((c >> 1) & 3) * 32 + (c >> 3) * 2 + (c & 1);
        Wd[(i >> 7) * 128 + perm] = pack2(w, w);
    }
    if (tid < C_MID) { s1s[tid] = g_s1[tid]; t1s[tid] = g_t1[tid]; }
    if (tid < C_OUT) { sW[tid] = 0.f; sQ[tid] = 0.f; }
    float bc[8];
    {
        float4 ba = *(const float4*)(b2 + c0);
        float4 bb = *(const float4*)(b2 + c0 + 4);
        bc[0]=ba.x; bc[1]=ba.y; bc[2]=ba.z; bc[3]=ba.w;
        bc[4]=bb.x; bc[5]=bb.y; bc[6]=bb.z; bc[7]=bb.w;
    }
    float wsum[8] = {0,0,0,0,0,0,0,0}, wsq[8] = {0,0,0,0,0,0,0,0};
    int ntiles = (n + 127) >> 7;
    uint4 pf[4];
    int tile = blockIdx.x;
    if (tile < ntiles) {
        int gr = (tile << 7) + lr; if (gr >= n) gr = n - 1;
        const uint4* p = (const uint4*)(g_Yh + (size_t)gr * C_MID + dh);
        #pragma unroll
        for (int u = 0; u < 4; u++) pf[u] = p[u];
    }
    for (; tile < ntiles; tile += gridDim.x) {
        int rbase = tile << 7;
        #pragma unroll
        for (int u = 0; u < 4; u++) {       // BN1+relu fused, conflict-free STS
            unsigned hw[4] = { pf[u].x, pf[u].y, pf[u].z, pf[u].w };
            int db = dh + (u << 3);
            #pragma unroll
            for (int q = 0; q < 4; q++) {
                float2 f = __half22float2(*reinterpret_cast<__half2*>(&hw[q]));
                int d = db + (q << 1);
                hs[(d + 0) * T2_PAD + lr] = fmaxf(fmaf(f.x, s1s[d + 0], t1s[d + 0]), 0.f);
                hs[(d + 1) * T2_PAD + lr] = fmaxf(fmaf(f.y, s1s[d + 1], t1s[d + 1]), 0.f);
            }
        }
        if (tid < 128) {
            int gr = rbase + tid;
            cnts[tid] = (gr < n) ? (float)g_cnt[gr] : 0.f;
        }
        __syncthreads();
        int nt = tile + gridDim.x;
        if (nt < ntiles) {
            int gr = (nt << 7) + lr; if (gr >= n) gr = n - 1;
            const uint4* p = (const uint4*)(g_Yh + (size_t)gr * C_MID + dh);
            #pragma unroll
            for (int u = 0; u < 4; u++) pf[u] = p[u];
        }
        ull acc[4][8];
        #pragma unroll
        for (int rp = 0; rp < 4; rp++)
            #pragma unroll
            for (int j = 0; j < 8; j++) acc[rp][j] = pack2(bc[j], bc[j]);
        #pragma unroll 8
        for (int d = 0; d < C_MID; d++) {
            ulonglong2 xA = *(const ulonglong2*)&hs[d * T2_PAD + r0];
            ulonglong2 xB = *(const ulonglong2*)&hs[d * T2_PAD + r0 + 4];
            ull xp[4] = { xA.x, xA.y, xB.x, xB.y };
            ulonglong2 w0 = *(const ulonglong2*)&Wd[d * 128 + 2 * tx];
            ulonglong2 w1 = *(const ulonglong2*)&Wd[d * 128 + 32 + 2 * tx];
            ulonglong2 w2 = *(const ulonglong2*)&Wd[d * 128 + 64 + 2 * tx];
            ulonglong2 w3 = *(const ulonglong2*)&Wd[d * 128 + 96 + 2 * tx];
            ull wd[8] = { w0.x, w0.y, w1.x, w1.y, w2.x, w2.y, w3.x, w3.y };
            #pragma unroll
            for (int rp = 0; rp < 4; rp++)
                #pragma unroll
                for (int j = 0; j < 8; j++)
                    acc[rp][j] = fma2(xp[rp], wd[j], acc[rp][j]);
        }
        #pragma unroll
        for (int rp = 0; rp < 4; rp++) {
            int rA = rbase + r0 + (rp << 1);
            float za[8], zb[8];
            #pragma unroll
            for (int j = 0; j < 8; j++) unpack2(acc[rp][j], za[j], zb[j]);
            if (rA < n) {
                __half2 h0 = __floats2half2_rn(za[0], za[1]);
                __half2 h1 = __floats2half2_rn(za[2], za[3]);
                __half2 h2 = __floats2half2_rn(za[4], za[5]);
                __half2 h3 = __floats2half2_rn(za[6], za[7]);
                uint4 u;
                u.x = *reinterpret_cast<unsigned*>(&h0); u.y = *reinterpret_cast<unsigned*>(&h1);
                u.z = *reinterpret_cast<unsigned*>(&h2); u.w = *reinterpret_cast<unsigned*>(&h3);
                *(uint4*)(g_Zh + (size_t)rA * C_OUT + c0) = u;
                float w = cnts[r0 + (rp << 1)];
                #pragma unroll
                for (int j = 0; j < 8; j++) {
                    wsum[j] = fmaf(w, za[j], wsum[j]);
                    wsq[j]  = fmaf(w, za[j] * za[j], wsq[j]);
                }
            }
            if (rA + 1 < n) {
                __half2 h0 = __floats2half2_rn(zb[0], zb[1]);
                __half2 h1 = __floats2half2_rn(zb[2], zb[3]);
                __half2 h2 = __floats2half2_rn(zb[4], zb[5]);
                __half2 h3 = __floats2half2_rn(zb[6], zb[7]);
                uint4 u;
                u.x = *reinterpret_cast<unsigned*>(&h0); u.y = *reinterpret_cast<unsigned*>(&h1);
                u.z = *reinterpret_cast<unsigned*>(&h2); u.w = *reinterpret_cast<unsigned*>(&h3);
                *(uint4*)(g_Zh + (size_t)(rA + 1) * C_OUT + c0) = u;
                float w = cnts[r0 + (rp << 1) + 1];
                #pragma unroll
                for (int j = 0; j < 8; j++) {
                    wsum[j] = fmaf(w, zb[j], wsum[j]);
                    wsq[j]  = fmaf(w, zb[j] * zb[j], wsq[j]);
                }
            }
        }
        __syncthreads();
    }
    #pragma unroll
    for (int j = 0; j < 8; j++) {
        atomicAdd(&sW[c0 + j], wsum[j]);
        atomicAdd(&sQ[c0 + j], wsq[j]);
    }
    __syncthreads();
    if (tid < C_OUT) {
        atomicAdd(&g_sum2[tid], sW[tid]);
        atomicAdd(&g_sq2[tid],  sQ[tid]);
    }
}

__global__ void finalize2_kernel(const float* __restrict__ g2,
                                 const float* __restrict__ be2, float invN) {
    int c = threadIdx.x;  // 128
    float mu  = g_sum2[c] * invN;
    float var = g_sq2[c] * invN - mu * mu;
    float s = g2[c] * rsqrtf(var + EPS_BN);
    g_s2[c] = s;
    g_t2[c] = be2[c] - mu * s;
}

// ---------------------------------------------------------------------------
// out[i,c] = max_k relu(Zh[idx[i,k],c]*s2[c] + t2[c]).
__global__ void __launch_bounds__(256) gather_max_kernel(const void* __restrict__ idxp,
        float* __restrict__ out, int n, int k) {
    __shared__ int ridx[4][32];
    int tid = threadIdx.x;
    int g  = tid >> 6;      // point slot 0..3
    int c2 = tid & 63;      // half2 channel index
    int i = blockIdx.x * 4 + g;
    bool valid = i < n;
    if (valid && c2 < k) {
        if (g_is64) ridx[g][c2] = (int)((const long long*)idxp)[(size_t)i * k + c2];
        else        ridx[g][c2] = ((const int*)idxp)[(size_t)i * k + c2];
    }
    float2 s = *(const float2*)&g_s2[c2 * 2];
    float2 t = *(const float2*)&g_t2[c2 * 2];
    __syncthreads();
    if (!valid) return;
    float m0 = 0.f, m1 = 0.f;   // relu lower bound
    #pragma unroll 8
    for (int j = 0; j < k; j++) {
        __half2 h = *(const __half2*)(g_Zh + (size_t)ridx[g][j] * C_OUT + c2 * 2);
        float2 z = __half22float2(h);
        m0 = fmaxf(m0, fmaf(z.x, s.x, t.x));
        m1 = fmaxf(m1, fmaf(z.y, s.y, t.y));
    }
    *(float2*)(out + (size_t)i * C_OUT + c2 * 2) = make_float2(m0, m1);
}

// ---------------------------------------------------------------------------
extern "C" void kernel_launch(void* const* d_in, const int* in_sizes, int n_in,
                              void* d_out, int out_size) {
    const float* feat = (const float*)d_in[0];
    const void*  idx  = d_in[1];
    const float* W1   = (const float*)d_in[2];
    const float* b1   = (const float*)d_in[3];
    const float* g1   = (const float*)d_in[4];
    const float* be1  = (const float*)d_in[5];
    const float* W2   = (const float*)d_in[6];
    const float* b2   = (const float*)d_in[7];
    const float* g2   = (const float*)d_in[8];
    const float* be2  = (const float*)d_in[9];
    float* out = (float*)d_out;

    int n = in_sizes[0] / C_IN;       // 100000
    int k = in_sizes[1] / n;          // 16
    int total = n * k;                // 1.6M
    float invN = 1.0f / (float)total;

    static bool attr_done = false;
    if (!attr_done) {
        cudaFuncSetAttribute(gemm1_kernel, cudaFuncAttributeMaxDynamicSharedMemorySize,
                             SMEM1_BYTES);
        cudaFuncSetAttribute(gemm2_kernel, cudaFuncAttributeMaxDynamicSharedMemorySize,
                             SMEM2_BYTES);
        attr_done = true;
    }

    zero_kernel<<<(n + 255) / 256, 256>>>(n);
    detect_kernel<<<1, 1024>>>(idx);
    hist_kernel<<<(total + 255) / 256, 256>>>(idx, total);
    gemm1_kernel<<<296, 256, SMEM1_BYTES>>>(feat, W1, b1, n);
    finalize1_kernel<<<1, C_MID>>>(g1, be1, invN);
    gemm2_kernel<<<296, 256, SMEM2_BYTES>>>(W2, b2, n);
    finalize2_kernel<<<1, C_OUT>>>(g2, be2, invN);
    gather_max_kernel<<<(n + 3) / 4, 256>>>(idx, out, n, k);
}